// round 16
// baseline (speedup 1.0000x reference)
#include <cuda_runtime.h>
#include <cuda_bf16.h>

// R14 champion restored (ETB=512, 15.1us). ETB=1024 regressed (R15): block
// granularity optimum is 512. Micro: REDUX.SYNC for the u32 warp reduction.
//
// Edge atomicAdd RETURNS old packed value -> exact integer marginal:
//   node state (u64): [63:56] z | [55:48] m | [47:24] Cfix | [23:0] Sfix
//     Cfix += round((cos4t+1)*8192); Chat := Cfix - 8192*m (exact)
//   d(m^2*2^26 - Chat^2 - Shat^2) = (2m+1)<<26 - ch*(2Chat+ch) - sh*(2Shat+sh)
//   d(P) = deg_old,  deg = m + z
// loss = num_fix / (2^30 * P). Second kernel: zero-fill + finalize (PDL-hidden).

#define MAXN 65536
#define ETB 512

__device__ __align__(16) unsigned long long g_acc[MAXN];
__device__ unsigned long long g_numfix;   // two's-complement int64 sum
__device__ unsigned g_p;                  // sum deg(deg-1)/2

__global__ void __launch_bounds__(ETB)
edge_kernel(const float2* __restrict__ pos,
            const int* __restrict__ src,
            const int* __restrict__ dst,
            int E) {
    int e = blockIdx.x * ETB + threadIdx.x;
    long long num = 0;
    unsigned p = 0;
    if (e < E) {
        int a = __ldg(src + e);
        int b = __ldg(dst + e);
        float2 pa = __ldg(pos + a);
        float2 pb = __ldg(pos + b);
        float dx = pb.x - pa.x;
        float dy = pb.y - pa.y;
        float n2 = dx * dx + dy * dy;

        unsigned long long payload;
        int ch = 0, sh = 0;
        bool unit = (n2 > 0.f);
        if (unit) {
            float inv = rsqrtf(n2);
            float c = dx * inv, s = dy * inv;
            float c2 = c * c - s * s;
            float s2 = 2.f * c * s;
            float c4 = c2 * c2 - s2 * s2;
            float s4 = 2.f * c2 * s2;
            unsigned cf = __float2uint_rn(fmaxf((c4 + 1.f) * 8192.f, 0.f));
            unsigned sf = __float2uint_rn(fmaxf((s4 + 1.f) * 8192.f, 0.f));
            payload = (1ULL << 48) | ((unsigned long long)cf << 24) | sf;
            ch = (int)cf - 8192;
            sh = (int)sf - 8192;
        } else {
            payload = 1ULL << 56;   // zero-length slot: z += 1
        }

        unsigned long long oa = atomicAdd(&g_acc[a], payload);
        unsigned long long ob = atomicAdd(&g_acc[b], payload);

        #pragma unroll
        for (int k = 0; k < 2; k++) {
            unsigned long long o = k ? ob : oa;
            int m = (int)((o >> 48) & 0xFFULL);
            int z = (int)(o >> 56);
            p += (unsigned)(m + z);                     // deg_old
            if (unit) {
                int C24 = (int)((o >> 24) & 0xFFFFFFULL);
                int S24 = (int)(o & 0xFFFFFFULL);
                int Chat = C24 - (m << 13);
                int Shat = S24 - (m << 13);
                num += ((long long)(2 * m + 1) << 26)
                     - (long long)ch * (2 * Chat + ch)
                     - (long long)sh * (2 * Shat + sh);
            }
        }
    }

#if __CUDA_ARCH__ >= 900
    // Early trigger: atomics issued; dependent launch setup overlaps the
    // block-reduce tail below (its gridDepSync still waits for completion).
    cudaTriggerProgrammaticLaunchCompletion();
#endif

    // ---- block reduce ----
    p = __reduce_add_sync(0xffffffffu, p);     // REDUX.SYNC.ADD
    #pragma unroll
    for (int off = 16; off > 0; off >>= 1) {
        num += __shfl_down_sync(0xffffffffu, num, off);
    }
    __shared__ long long sh_num[ETB / 32];
    __shared__ unsigned sh_p[ETB / 32];
    int lane = threadIdx.x & 31;
    int wid  = threadIdx.x >> 5;
    if (lane == 0) { sh_num[wid] = num; sh_p[wid] = p; }
    __syncthreads();
    if (wid == 0) {
        num = (lane < ETB / 32) ? sh_num[lane] : 0LL;
        p   = (lane < ETB / 32) ? sh_p[lane]   : 0u;
        p = __reduce_add_sync(0xffffffffu, p);
        #pragma unroll
        for (int off = 8; off > 0; off >>= 1) {
            num += __shfl_down_sync(0xffffffffu, num, off);
        }
        if (lane == 0) {
            atomicAdd(&g_numfix, (unsigned long long)num);  // mod-2^64 int64 add
            atomicAdd(&g_p, p);
        }
    }
}

__global__ void clean_finalize_kernel(float* __restrict__ out, int nq) {
#if __CUDA_ARCH__ >= 900
    cudaGridDependencySynchronize();   // all edge atomics + block sums visible
#endif
    int stride = gridDim.x * blockDim.x;
    for (int i = blockIdx.x * blockDim.x + threadIdx.x; i < nq; i += stride) {
        reinterpret_cast<ulonglong2*>(g_acc)[i] = make_ulonglong2(0ULL, 0ULL);
    }
    if (blockIdx.x == 0 && threadIdx.x == 0) {
        long long num_fix = (long long)g_numfix;
        double P = (double)g_p;
        // loss = (num_fix / 2^26) / (16 * P) = num_fix / (2^30 * P)
        out[0] = (P > 0.0) ? (float)((double)num_fix / (1073741824.0 * P)) : 0.0f;
        g_numfix = 0ULL;    // reset for next graph replay
        g_p = 0u;
    }
}

extern "C" void kernel_launch(void* const* d_in, const int* in_sizes, int n_in,
                              void* d_out, int out_size) {
    const float* pos = (const float*)d_in[0];       // (1, N, 2)
    const int* edge_index = (const int*)d_in[2];    // (2, E)
    int N = in_sizes[0] / 2;
    int E = in_sizes[2] / 2;
    const int* src = edge_index;
    const int* dst = edge_index + E;
    float* out = (float*)d_out;

    edge_kernel<<<(E + ETB - 1) / ETB, ETB>>>((const float2*)pos, src, dst, E);

    // PDL: cleanup/finalize launch overlaps edge_kernel's tail.
    int nq = (N + 1) / 2;   // ulonglong2 count covering all N nodes
    cudaLaunchConfig_t cfg = {};
    cfg.gridDim  = dim3(64);
    cfg.blockDim = dim3(256);
    cfg.dynamicSmemBytes = 0;
    cfg.stream = 0;
    cudaLaunchAttribute attr[1];
    attr[0].id = cudaLaunchAttributeProgrammaticStreamSerialization;
    attr[0].val.programmaticStreamSerializationAllowed = 1;
    cfg.attrs = attr;
    cfg.numAttrs = 1;
    cudaLaunchKernelEx(&cfg, clean_finalize_kernel, out, nq);
}

// round 17
// speedup vs baseline: 1.1189x; 1.1189x over previous
#include <cuda_runtime.h>
#include <cuda_bf16.h>

// R14 champion, byte-exact resubmission (reproducibility test: R14 measured
// 15.1us; R16 with only post-trigger tail changes measured 16.86us — decide
// whether 15.1 was real or a favorable timing bin).
//
// Edge atomicAdd RETURNS old packed value -> exact integer marginal:
//   node state (u64): [63:56] z | [55:48] m | [47:24] Cfix | [23:0] Sfix
//     Cfix += round((cos4t+1)*8192); Chat := Cfix - 8192*m (exact)
//   d(m^2*2^26 - Chat^2 - Shat^2) = (2m+1)<<26 - ch*(2Chat+ch) - sh*(2Shat+sh)
//   d(P) = deg_old,  deg = m + z
// loss = num_fix / (2^30 * P). Second kernel: zero-fill + finalize (PDL-hidden).

#define MAXN 65536
#define ETB 512

__device__ __align__(16) unsigned long long g_acc[MAXN];
__device__ unsigned long long g_numfix;   // two's-complement int64 sum
__device__ unsigned g_p;                  // sum deg(deg-1)/2

__global__ void __launch_bounds__(ETB)
edge_kernel(const float2* __restrict__ pos,
            const int* __restrict__ src,
            const int* __restrict__ dst,
            int E) {
    int e = blockIdx.x * ETB + threadIdx.x;
    long long num = 0;
    int p = 0;
    if (e < E) {
        int a = __ldg(src + e);
        int b = __ldg(dst + e);
        float2 pa = __ldg(pos + a);
        float2 pb = __ldg(pos + b);
        float dx = pb.x - pa.x;
        float dy = pb.y - pa.y;
        float n2 = dx * dx + dy * dy;

        unsigned long long payload;
        int ch = 0, sh = 0;
        bool unit = (n2 > 0.f);
        if (unit) {
            float inv = rsqrtf(n2);
            float c = dx * inv, s = dy * inv;
            float c2 = c * c - s * s;
            float s2 = 2.f * c * s;
            float c4 = c2 * c2 - s2 * s2;
            float s4 = 2.f * c2 * s2;
            unsigned cf = __float2uint_rn(fmaxf((c4 + 1.f) * 8192.f, 0.f));
            unsigned sf = __float2uint_rn(fmaxf((s4 + 1.f) * 8192.f, 0.f));
            payload = (1ULL << 48) | ((unsigned long long)cf << 24) | sf;
            ch = (int)cf - 8192;
            sh = (int)sf - 8192;
        } else {
            payload = 1ULL << 56;   // zero-length slot: z += 1
        }

        unsigned long long oa = atomicAdd(&g_acc[a], payload);
        unsigned long long ob = atomicAdd(&g_acc[b], payload);

        #pragma unroll
        for (int k = 0; k < 2; k++) {
            unsigned long long o = k ? ob : oa;
            int m = (int)((o >> 48) & 0xFFULL);
            int z = (int)(o >> 56);
            p += m + z;                                 // deg_old
            if (unit) {
                int C24 = (int)((o >> 24) & 0xFFFFFFULL);
                int S24 = (int)(o & 0xFFFFFFULL);
                int Chat = C24 - (m << 13);
                int Shat = S24 - (m << 13);
                num += ((long long)(2 * m + 1) << 26)
                     - (long long)ch * (2 * Chat + ch)
                     - (long long)sh * (2 * Shat + sh);
            }
        }
    }

#if __CUDA_ARCH__ >= 900
    // Early trigger: atomics issued; dependent launch setup overlaps the
    // block-reduce tail below (its gridDepSync still waits for full completion).
    cudaTriggerProgrammaticLaunchCompletion();
#endif

    // ---- block reduce ----
    #pragma unroll
    for (int off = 16; off > 0; off >>= 1) {
        num += __shfl_down_sync(0xffffffffu, num, off);
        p   += __shfl_down_sync(0xffffffffu, p, off);
    }
    __shared__ long long sh_num[ETB / 32];
    __shared__ int sh_p[ETB / 32];
    int lane = threadIdx.x & 31;
    int wid  = threadIdx.x >> 5;
    if (lane == 0) { sh_num[wid] = num; sh_p[wid] = p; }
    __syncthreads();
    if (wid == 0) {
        num = (lane < ETB / 32) ? sh_num[lane] : 0LL;
        p   = (lane < ETB / 32) ? sh_p[lane]   : 0;
        #pragma unroll
        for (int off = 8; off > 0; off >>= 1) {
            num += __shfl_down_sync(0xffffffffu, num, off);
            p   += __shfl_down_sync(0xffffffffu, p, off);
        }
        if (lane == 0) {
            atomicAdd(&g_numfix, (unsigned long long)num);  // mod-2^64 int64 add
            atomicAdd(&g_p, (unsigned)p);
        }
    }
}

__global__ void clean_finalize_kernel(float* __restrict__ out, int nq) {
#if __CUDA_ARCH__ >= 900
    cudaGridDependencySynchronize();   // all edge atomics + block sums visible
#endif
    int stride = gridDim.x * blockDim.x;
    for (int i = blockIdx.x * blockDim.x + threadIdx.x; i < nq; i += stride) {
        reinterpret_cast<ulonglong2*>(g_acc)[i] = make_ulonglong2(0ULL, 0ULL);
    }
    if (blockIdx.x == 0 && threadIdx.x == 0) {
        long long num_fix = (long long)g_numfix;
        double P = (double)g_p;
        // loss = (num_fix / 2^26) / (16 * P) = num_fix / (2^30 * P)
        out[0] = (P > 0.0) ? (float)((double)num_fix / (1073741824.0 * P)) : 0.0f;
        g_numfix = 0ULL;    // reset for next graph replay
        g_p = 0u;
    }
}

extern "C" void kernel_launch(void* const* d_in, const int* in_sizes, int n_in,
                              void* d_out, int out_size) {
    const float* pos = (const float*)d_in[0];       // (1, N, 2)
    const int* edge_index = (const int*)d_in[2];    // (2, E)
    int N = in_sizes[0] / 2;
    int E = in_sizes[2] / 2;
    const int* src = edge_index;
    const int* dst = edge_index + E;
    float* out = (float*)d_out;

    edge_kernel<<<(E + ETB - 1) / ETB, ETB>>>((const float2*)pos, src, dst, E);

    // PDL: cleanup/finalize launch overlaps edge_kernel's tail.
    int nq = (N + 1) / 2;   // ulonglong2 count covering all N nodes
    cudaLaunchConfig_t cfg = {};
    cfg.gridDim  = dim3(64);
    cfg.blockDim = dim3(256);
    cfg.dynamicSmemBytes = 0;
    cfg.stream = 0;
    cudaLaunchAttribute attr[1];
    attr[0].id = cudaLaunchAttributeProgrammaticStreamSerialization;
    attr[0].val.programmaticStreamSerializationAllowed = 1;
    cfg.attrs = attr;
    cfg.numAttrs = 1;
    cudaLaunchKernelEx(&cfg, clean_finalize_kernel, out, nq);
}